// round 17
// baseline (speedup 1.0000x reference)
#include <cuda_runtime.h>

// Problem constants
#define NB   2
#define C    128
#define H    64
#define WID  64
#define HW   4096       // H*W
#define KK   81         // L*L
#define PADR 4          // L/2

// fused kernel tiling (2x16 px tiles -> 256 blocks, 288 threads)
#define BTH  2
#define BTW  16
#define BTP  32         // px per tile
#define BHY  10         // 2 + 8 halo rows
#define BKST 28         // padded halo row stride
#define CSTR (BHY*BKST) // 280: channel stride in halo buffer
#define CCB  16         // B channel chunk (double-buffered)
#define SIMN 2592       // BTP*KK
#define WDS  36         // wd row stride

// fused smem layout (float offsets)
#define OF_WD   0
#define OF_KS   2916                  // B: 2 x 4480; D: 32ch x 280 = 8960
#define KSB16   4480                  // CCB*CSTR
#define OF_QS   11876                 // 2 x 512
#define QSB16   512
#define OF_SIMP 12900                 // 2 x SIMN
#define SMF     18084                 // total floats (70.6 KB) -> 3 blocks/SM

#define GK   16         // gemm W k-chunk

// Scratch (allocation-free rule: __device__ globals)
__device__ float g_key   [NB * C * HW];
__device__ float g_query [NB * C * HW];

// ---- packed fp32x2 helpers ----
typedef unsigned long long u64;
__device__ __forceinline__ u64 pk(float lo, float hi) {
    u64 r; asm("mov.b64 %0, {%1, %2};" : "=l"(r) : "f"(lo), "f"(hi)); return r;
}
__device__ __forceinline__ void fma2(u64& d, u64 a, u64 b) {
    asm("fma.rn.f32x2 %0, %1, %2, %0;" : "+l"(d) : "l"(a), "l"(b));
}
__device__ __forceinline__ float2 upk(u64 v) {
    float2 r; asm("mov.b64 {%0, %1}, %2;" : "=f"(r.x), "=f"(r.y) : "l"(v)); return r;
}

// ---- cp.async helpers (16B granules) ----
__device__ __forceinline__ void cp16(unsigned saddr, const void* g) {
    asm volatile("cp.async.cg.shared.global [%0], [%1], 16;" :: "r"(saddr), "l"(g));
}
#define CP_COMMIT() asm volatile("cp.async.commit_group;" ::: "memory")
#define CP_WAIT0()  asm volatile("cp.async.wait_group 0;" ::: "memory")

// ---------------------------------------------------------------------------
// Kernel A: 1x1-conv projections (R8 version — proven).
// ---------------------------------------------------------------------------
__global__ __launch_bounds__(256) void gemm_kernel(
        const float* __restrict__ ft, const float* __restrict__ fk,
        const float* __restrict__ Wm)
{
    extern __shared__ float sm[];
    float* Xs = sm;                 // [128][64]
    float* Ws = sm + 128 * 64;      // [2][GK][128]

    const int t  = threadIdx.x;
    const int p0 = blockIdx.x * 64;
    const int n  = blockIdx.y & 1;
    const int which = blockIdx.y >> 1;
    const float* X = (which ? fk : ft) + n * C * HW;
    float*       Y = (which ? g_query : g_key) + n * C * HW;

    const int px  = (t & 15) * 4;
    const int co8 = (t >> 4) * 8;

    {
        const int cc = t >> 4;
        const int xp = (t & 15) * 4;
        #pragma unroll
        for (int it = 0; it < 8; it++) {
            int c = cc + it * 16;
            *(float4*)&Xs[c * 64 + xp] = *(const float4*)&X[c * HW + p0 + xp];
        }
    }
    const int so  = t >> 1;
    const int sk4 = (t & 1) * 8;
    auto stageW = [&](int buf, int kb) {
        float* Wb = Ws + buf * (GK * 128);
        #pragma unroll
        for (int j = 0; j < 2; j++) {
            int k4 = sk4 + j * 4;
            float4 wv = *(const float4*)&Wm[so * C + kb + k4];
            Wb[(k4 + 0) * 128 + so] = wv.x;
            Wb[(k4 + 1) * 128 + so] = wv.y;
            Wb[(k4 + 2) * 128 + so] = wv.z;
            Wb[(k4 + 3) * 128 + so] = wv.w;
        }
    };
    stageW(0, 0);

    u64 acc[4][4] = {};
    __syncthreads();

    int buf = 0;
    for (int kb = 0; kb < 8; kb++) {
        if (kb < 7) stageW(buf ^ 1, (kb + 1) * GK);
        const float* Wb = Ws + buf * (GK * 128);
        const float* Xb = Xs + (kb * GK) * 64;
        #pragma unroll
        for (int kk = 0; kk < GK; kk++) {
            float4 a0 = *(const float4*)&Wb[kk * 128 + co8];
            float4 a1 = *(const float4*)&Wb[kk * 128 + co8 + 4];
            float4 b  = *(const float4*)&Xb[kk * 64 + px];
            u64 ap0 = pk(a0.x, a0.y), ap1 = pk(a0.z, a0.w);
            u64 ap2 = pk(a1.x, a1.y), ap3 = pk(a1.z, a1.w);
            u64 b0 = pk(b.x, b.x), b1 = pk(b.y, b.y);
            u64 b2 = pk(b.z, b.z), b3 = pk(b.w, b.w);
            fma2(acc[0][0], ap0, b0); fma2(acc[0][1], ap0, b1);
            fma2(acc[0][2], ap0, b2); fma2(acc[0][3], ap0, b3);
            fma2(acc[1][0], ap1, b0); fma2(acc[1][1], ap1, b1);
            fma2(acc[1][2], ap1, b2); fma2(acc[1][3], ap1, b3);
            fma2(acc[2][0], ap2, b0); fma2(acc[2][1], ap2, b1);
            fma2(acc[2][2], ap2, b2); fma2(acc[2][3], ap2, b3);
            fma2(acc[3][0], ap3, b0); fma2(acc[3][1], ap3, b1);
            fma2(acc[3][2], ap3, b2); fma2(acc[3][3], ap3, b3);
        }
        __syncthreads();
        buf ^= 1;
    }

    #pragma unroll
    for (int j2 = 0; j2 < 4; j2++) {
        float2 v0 = upk(acc[j2][0]), v1 = upk(acc[j2][1]);
        float2 v2 = upk(acc[j2][2]), v3 = upk(acc[j2][3]);
        *(float4*)&Y[(co8 + 2 * j2)     * HW + p0 + px] =
            make_float4(v0.x, v1.x, v2.x, v3.x);
        *(float4*)&Y[(co8 + 2 * j2 + 1) * HW + p0 + px] =
            make_float4(v0.y, v1.y, v2.y, v3.y);
    }
}

// ---------------------------------------------------------------------------
// Fused kernel v3: sim + softmax + weighting.
//  - 70.6 KB smem, __launch_bounds__(288,3): 3 blocks/SM (27 warps).
//  - staging via 16B cp.async granules with precomputed validity mask
//    (halo columns are 4-float aligned vs borders -> whole-granule validity).
//  - Phase B: 8 chunks of 16 ch, double-buffered pipeline.
//  - Phase D: 4 chunks of 32 ch in the same ks region; chunk 0 staged during
//    merge+softmax; later stage-stalls hidden by co-resident blocks.
// ---------------------------------------------------------------------------
__global__ void __launch_bounds__(288, 3) fused_kernel(
        const float* __restrict__ ft, float* __restrict__ out)
{
    extern __shared__ float sm[];
    float* wd     = sm + OF_WD;     // [81][36]
    float* ksbase = sm + OF_KS;
    float* qsbase = sm + OF_QS;
    float* simp   = sm + OF_SIMP;   // [2][SIMN]

    const int t   = threadIdx.x;
    const int bx  = blockIdx.x;
    const int n   = bx >> 7;
    const int rem = bx & 127;
    const int ty0 = (rem >> 2) * BTH;
    const int tx0 = (rem & 3) * BTW;

    const float* keyg = g_key   + n * C * HW;
    const float* qg   = g_query + n * C * HW;
    const float* ftn  = ft      + n * C * HW;

    // ---- staging precompute (fixed per thread) ----
    // t < 160: halo unit (ch = t/10 in chunk, row = t%10), 6 x 16B granules
    // t >= 160: query unit (128 units: ch*8 granules)
    const int kch  = t / 10;
    const int krow = t - kch * 10;
    const int kgy  = ty0 + krow - PADR;
    const int gx0  = tx0 - PADR;
    const bool rowok = (unsigned)kgy < H;
    unsigned vm = 0;
    #pragma unroll
    for (int g = 0; g < 6; g++)
        if (rowok && (unsigned)(gx0 + 4 * g) < WID) vm |= 1u << g;
    const int kgoff = kgy * WID + gx0;
    const int ksoff = kch * CSTR + krow * BKST;
    const unsigned ks_sh0 = (unsigned)__cvta_generic_to_shared(ksbase) + ksoff * 4;

    const int qu   = t - 160;            // valid if t >= 160
    const int qch  = (qu >> 3) & 15;
    const int qrow = (qu >> 2) & 1;
    const int qseg = qu & 3;
    const int qgoff = (ty0 + qrow) * WID + tx0 + qseg * 4;
    const int qsoff = qch * 32 + qrow * 16 + qseg * 4;
    const unsigned qs_sh0 = (unsigned)__cvta_generic_to_shared(qsbase) + qsoff * 4;

    const int cq  = t / 72;
    const int r   = t - cq * 72;
    const int di  = r >> 3;
    const int pxg = r & 7;
    const int ly  = pxg >> 2;
    const int lxg = (pxg & 3) * 4;

    auto stageB = [&](int buf, int cc) {
        if (t < 160) {
            const float* s = keyg + (cc + kch) * HW + kgoff;
            unsigned dsh = ks_sh0 + buf * (KSB16 * 4);
            float* dz = ksbase + buf * KSB16 + ksoff;
            #pragma unroll
            for (int g = 0; g < 6; g++) {
                if ((vm >> g) & 1) cp16(dsh + g * 16, s + g * 4);
                else *(float4*)(dz + g * 4) = make_float4(0.f, 0.f, 0.f, 0.f);
            }
        } else {
            cp16(qs_sh0 + buf * (QSB16 * 4), qg + (cc + qch) * HW + qgoff);
        }
        CP_COMMIT();
    };
    auto stageD = [&](int cc) {          // 32 channels into full ks region
        if (t < 160) {
            const float* s0 = ftn + (cc + kch) * HW + kgoff;
            const float* s1 = s0 + 16 * HW;
            float* dz0 = ksbase + ksoff;
            float* dz1 = dz0 + 16 * CSTR;
            #pragma unroll
            for (int g = 0; g < 6; g++) {
                if ((vm >> g) & 1) {
                    cp16(ks_sh0 + g * 16, s0 + g * 4);
                    cp16(ks_sh0 + 16 * CSTR * 4 + g * 16, s1 + g * 4);
                } else {
                    *(float4*)(dz0 + g * 4) = make_float4(0.f, 0.f, 0.f, 0.f);
                    *(float4*)(dz1 + g * 4) = make_float4(0.f, 0.f, 0.f, 0.f);
                }
            }
        }
        CP_COMMIT();
    };

    u64 accp[9][2] = {};

    // ===================== Phase B: sim (pipelined, 8x16ch) ================
    stageB(0, 0);
    CP_WAIT0();
    __syncthreads();
    for (int i = 0; i < 8; i++) {
        if (i < 7) stageB((i + 1) & 1, (i + 1) * CCB);
        const float* ks = ksbase + (i & 1) * KSB16;
        const float* qs = qsbase + (i & 1) * QSB16;
        const int cbeg = cq * 4;
        #pragma unroll
        for (int c = cbeg; c < cbeg + 4; c++) {
            float4 q4 = *(const float4*)&qs[c * BTP + ly * BTW + lxg];
            const float* kp = &ks[c * CSTR + (ly + di) * BKST + lxg];
            float4 k0 = *(const float4*)kp;
            float4 k1 = *(const float4*)(kp + 4);
            float4 k2 = *(const float4*)(kp + 8);
            const float kr[12] = {k0.x, k0.y, k0.z, k0.w,
                                  k1.x, k1.y, k1.z, k1.w,
                                  k2.x, k2.y, k2.z, k2.w};
            u64 q01 = pk(q4.x, q4.y), q23 = pk(q4.z, q4.w);
            u64 win[11];
            #pragma unroll
            for (int m = 0; m < 11; m++) win[m] = pk(kr[m], kr[m + 1]);
            #pragma unroll
            for (int dj = 0; dj < 9; dj++) {
                fma2(accp[dj][0], q01, win[dj]);
                fma2(accp[dj][1], q23, win[dj + 2]);
            }
        }
        CP_WAIT0();
        __syncthreads();
    }

    // issue D chunk-0 staging now — overlaps merge + softmax
    stageD(0);

    // merge 4 partials into 2 arrays (cq0,1 -> sp0; cq2,3 -> sp1)
    const int pxb = ly * BTW + lxg;
    float* sp = simp + (cq >> 1) * SIMN;
    if ((cq & 1) == 0) {
        #pragma unroll
        for (int dj = 0; dj < 9; dj++) {
            float2 v0 = upk(accp[dj][0]), v1 = upk(accp[dj][1]);
            sp[(pxb + 0) * KK + di * 9 + dj] = v0.x;
            sp[(pxb + 1) * KK + di * 9 + dj] = v0.y;
            sp[(pxb + 2) * KK + di * 9 + dj] = v1.x;
            sp[(pxb + 3) * KK + di * 9 + dj] = v1.y;
        }
    }
    __syncthreads();
    if (cq & 1) {
        #pragma unroll
        for (int dj = 0; dj < 9; dj++) {
            float2 v0 = upk(accp[dj][0]), v1 = upk(accp[dj][1]);
            sp[(pxb + 0) * KK + di * 9 + dj] += v0.x;
            sp[(pxb + 1) * KK + di * 9 + dj] += v0.y;
            sp[(pxb + 2) * KK + di * 9 + dj] += v1.x;
            sp[(pxb + 3) * KK + di * 9 + dj] += v1.y;
        }
    }
    __syncthreads();

    // softmax over 81 taps -> transposed wd[81][36]
    if (t < 256) {
        const int px = t >> 3;
        const int q  = t & 7;
        float* r0 = &simp[px * KK];
        float* r1 = r0 + SIMN;
        float m = -1e30f;
        for (int k = q; k < KK; k += 8) {
            float v = r0[k] + r1[k];
            r0[k] = v;
            m = fmaxf(m, v);
        }
        m = fmaxf(m, __shfl_xor_sync(0xffffffffu, m, 1));
        m = fmaxf(m, __shfl_xor_sync(0xffffffffu, m, 2));
        m = fmaxf(m, __shfl_xor_sync(0xffffffffu, m, 4));
        float s = 0.f;
        for (int k = q; k < KK; k += 8) {
            float e = __expf(r0[k] - m);
            r0[k] = e;
            s += e;
        }
        s += __shfl_xor_sync(0xffffffffu, s, 1);
        s += __shfl_xor_sync(0xffffffffu, s, 2);
        s += __shfl_xor_sync(0xffffffffu, s, 4);
        const float inv = 1.f / s;
        for (int k = q; k < KK; k += 8)
            wd[k * WDS + px] = r0[k] * inv;
    }
    CP_WAIT0();
    __syncthreads();

    // ===================== Phase D: weighting (4 x 32ch) ==================
    const int dch = t >> 3;             // 0..31 (t < 256)
    float* on = out + n * C * HW;
    const int opix = (ty0 + ly) * WID + tx0 + lxg;

    #pragma unroll
    for (int j = 0; j < 4; j++) {
        const int cc = j * 32;
        if (t < 256) {
            u64 a0 = 0, a1 = 0;
            #pragma unroll
            for (int ddi = 0; ddi < 9; ddi++) {
                const float* f = &ksbase[dch * CSTR + (ly + ddi) * BKST + lxg];
                float4 x0 = *(const float4*)f;
                float4 x1 = *(const float4*)(f + 4);
                float4 x2 = *(const float4*)(f + 8);
                const float fr[12] = {x0.x, x0.y, x0.z, x0.w,
                                      x1.x, x1.y, x1.z, x1.w,
                                      x2.x, x2.y, x2.z, x2.w};
                u64 win[11];
                #pragma unroll
                for (int m = 0; m < 11; m++) win[m] = pk(fr[m], fr[m + 1]);
                #pragma unroll
                for (int dj = 0; dj < 9; dj++) {
                    float4 w4 = *(const float4*)&wd[(ddi * 9 + dj) * WDS + ly * BTW + lxg];
                    fma2(a0, pk(w4.x, w4.y), win[dj]);
                    fma2(a1, pk(w4.z, w4.w), win[dj + 2]);
                }
            }
            float2 v0 = upk(a0), v1 = upk(a1);
            *(float4*)&on[(cc + dch) * HW + opix] =
                make_float4(v0.x, v0.y, v1.x, v1.y);
        }
        if (j < 3) {
            __syncthreads();            // all reads of this chunk done
            stageD((j + 1) * 32);
            CP_WAIT0();
            __syncthreads();
        }
    }
}

// ---------------------------------------------------------------------------
extern "C" void kernel_launch(void* const* d_in, const int* in_sizes, int n_in,
                              void* d_out, int out_size)
{
    const float* ft = (const float*)d_in[0];
    const float* fk = (const float*)d_in[1];
    const float* Wm = (const float*)d_in[2];
    float* out = (float*)d_out;

    const int smA = (128 * 64 + 2 * GK * 128) * (int)sizeof(float);   // 49152
    const int smF = SMF * (int)sizeof(float);                          // 72336
    cudaFuncSetAttribute(gemm_kernel,
                         cudaFuncAttributeMaxDynamicSharedMemorySize, smA);
    cudaFuncSetAttribute(fused_kernel,
                         cudaFuncAttributeMaxDynamicSharedMemorySize, smF);

    gemm_kernel<<<dim3(HW / 64, 4), 256, smA>>>(ft, fk, Wm);
    fused_kernel<<<NB * (H / BTH) * (WID / BTW), 288, smF>>>(ft, out);
}